// round 1
// baseline (speedup 1.0000x reference)
#include <cuda_runtime.h>
#include <cstddef>

// ProdLayer forward: element_mars[nids] = node_mars[cids].sum(axis=1)
// Inputs (metadata order):
//   d_in[0] node_mars     float32  [N_SRC, B]        (N_SRC*B elements)
//   d_in[1] element_mars  float32  [N_PROD+1, B]
//   d_in[2] nids          int32    [N_PROD]
//   d_in[3] cids          int32    [N_PROD, 4]
// Output: float32 [N_PROD+1, B]
//
// B = 128 floats = 32 float4 per row. One warp per product row:
// lane l handles float4 column l. 4 independent LDG.128 per lane (MLP=4),
// one STG.128. cids row loaded as a uniform int4 (broadcast).
// Warp index == n_prod handles the reserved row 0 (copy from element_mars,
// since d_out is poisoned).

static constexpr int B_F4 = 32;  // 128 floats / 4

__global__ void __launch_bounds__(256) prodlayer_kernel(
    const float4* __restrict__ node_mars,   // as float4, row stride 32
    const float4* __restrict__ element_mars,
    const int*    __restrict__ nids,
    const int4*   __restrict__ cids,
    float4*       __restrict__ out,
    int n_prod)
{
    const int gwarp = (int)((blockIdx.x * (unsigned)blockDim.x + threadIdx.x) >> 5);
    const int lane  = threadIdx.x & 31;

    if (gwarp < n_prod) {
        const int4 c = __ldg(&cids[gwarp]);

        const float4 a = __ldg(&node_mars[(size_t)c.x * B_F4 + lane]);
        const float4 b = __ldg(&node_mars[(size_t)c.y * B_F4 + lane]);
        const float4 d = __ldg(&node_mars[(size_t)c.z * B_F4 + lane]);
        const float4 e = __ldg(&node_mars[(size_t)c.w * B_F4 + lane]);

        float4 s;
        s.x = (a.x + b.x) + (d.x + e.x);
        s.y = (a.y + b.y) + (d.y + e.y);
        s.z = (a.z + b.z) + (d.z + e.z);
        s.w = (a.w + b.w) + (d.w + e.w);

        const int o = __ldg(&nids[gwarp]);
        out[(size_t)o * B_F4 + lane] = s;
    } else if (gwarp == n_prod) {
        // Reserved row 0: out row 0 = element_mars row 0 (d_out is poisoned).
        out[lane] = __ldg(&element_mars[lane]);
    }
}

extern "C" void kernel_launch(void* const* d_in, const int* in_sizes, int n_in,
                              void* d_out, int out_size)
{
    const float4* node_mars    = (const float4*)d_in[0];
    const float4* element_mars = (const float4*)d_in[1];
    const int*    nids         = (const int*)d_in[2];
    const int4*   cids         = (const int4*)d_in[3];
    float4*       out          = (float4*)d_out;

    const int n_prod = in_sizes[2];           // 500000
    const int n_warps = n_prod + 1;           // +1 warp for the reserved row 0
    const int threads = 256;                  // 8 warps/block
    const int blocks  = (n_warps * 32 + threads - 1) / threads;

    prodlayer_kernel<<<blocks, threads>>>(node_mars, element_mars, nids, cids,
                                          out, n_prod);
}

// round 2
// speedup vs baseline: 1.0223x; 1.0223x over previous
#include <cuda_runtime.h>
#include <cstddef>

// ProdLayer forward: element_mars[nids] = node_mars[cids].sum(axis=1)
//   d_in[0] node_mars     float32  [N_SRC, 128]
//   d_in[1] element_mars  float32  [N_PROD+1, 128]
//   d_in[2] nids          int32    [N_PROD]
//   d_in[3] cids          int32    [N_PROD, 4]
// Output: float32 [N_PROD+1, 128]
//
// Warp-per-row, float4 lanes (R1). R2 change: output stores use __stcs
// (evict-first / streaming) so the 256 MB of write-once output does not
// write-allocate into L2 and evict gather rows; index reads use __ldcs.
// More L2 capacity for node_mars re-references -> fewer DRAM read misses.

static constexpr int B_F4 = 32;  // 128 floats / 4

__global__ void __launch_bounds__(256) prodlayer_kernel(
    const float4* __restrict__ node_mars,
    const float4* __restrict__ element_mars,
    const int*    __restrict__ nids,
    const int4*   __restrict__ cids,
    float4*       __restrict__ out,
    int n_prod)
{
    const int gwarp = (int)((blockIdx.x * (unsigned)blockDim.x + threadIdx.x) >> 5);
    const int lane  = threadIdx.x & 31;

    if (gwarp < n_prod) {
        const int4 c = __ldcs(&cids[gwarp]);      // streaming: no L2 reuse

        const float4 a = __ldg(&node_mars[(size_t)c.x * B_F4 + lane]);
        const float4 b = __ldg(&node_mars[(size_t)c.y * B_F4 + lane]);
        const float4 d = __ldg(&node_mars[(size_t)c.z * B_F4 + lane]);
        const float4 e = __ldg(&node_mars[(size_t)c.w * B_F4 + lane]);

        float4 s;
        s.x = (a.x + b.x) + (d.x + e.x);
        s.y = (a.y + b.y) + (d.y + e.y);
        s.z = (a.z + b.z) + (d.z + e.z);
        s.w = (a.w + b.w) + (d.w + e.w);

        const int o = __ldcs(&nids[gwarp]);
        __stcs(&out[(size_t)o * B_F4 + lane], s);  // evict-first streaming store
    } else if (gwarp == n_prod) {
        // Reserved row 0: out row 0 = element_mars row 0 (d_out is poisoned).
        __stcs(&out[lane], __ldcs(&element_mars[lane]));
    }
}

extern "C" void kernel_launch(void* const* d_in, const int* in_sizes, int n_in,
                              void* d_out, int out_size)
{
    const float4* node_mars    = (const float4*)d_in[0];
    const float4* element_mars = (const float4*)d_in[1];
    const int*    nids         = (const int*)d_in[2];
    const int4*   cids         = (const int4*)d_in[3];
    float4*       out          = (float4*)d_out;

    const int n_prod = in_sizes[2];           // 500000
    const int n_warps = n_prod + 1;           // +1 warp for the reserved row 0
    const int threads = 256;                  // 8 warps/block
    const int blocks  = (n_warps * 32 + threads - 1) / threads;

    prodlayer_kernel<<<blocks, threads>>>(node_mars, element_mars, nids, cids,
                                          out, n_prod);
}